// round 4
// baseline (speedup 1.0000x reference)
#include <cuda_runtime.h>

#define NB 4
#define NUM_OP 6
#define LANG_DIM 256
#define NHIDDEN 128
#define HH 128
#define WW 128
#define HWSZ (HH * WW)        // 16384
#define NC 128
#define SEM_CH (NUM_OP + 2)   // 8

__device__ float g_gw[NB][NUM_OP];
__device__ float g_bw[NB][NUM_OP];
__device__ float g_wrsum;
__device__ float g_br;

// ---------------------------------------------------------------------------
// Kernel 1: full coefficient chain in ONE block (512 threads = 16 warps).
//   actv[b][n] = bs[n] + lang[b,:].Ws[n,:]      (warp w: rows 8w..8w+7)
//   gw[b][k] = (bg[k] + actv[b,:].Wg[k,:])*Wr[k]  (warp k<6)
//   bw[b][k] = (bb[k] + actv[b,:].Wb[k,:])*Wr[k]
// All weight loads coalesced; Ws read exactly once.
// ---------------------------------------------------------------------------
__global__ __launch_bounds__(512) void coef_kernel(
    const float* __restrict__ lang,
    const float* __restrict__ Ws, const float* __restrict__ bs,
    const float* __restrict__ Wg, const float* __restrict__ bg,
    const float* __restrict__ Wb, const float* __restrict__ bb,
    const float* __restrict__ Wr, const float* __restrict__ br) {
    const int tid  = threadIdx.x;
    const int warp = tid >> 5;     // 0..15
    const int lane = tid & 31;

    __shared__ float slang[NB][LANG_DIM];
    __shared__ float actv[NB][NHIDDEN];

    // Stage all 4 lang vectors (1024 floats, coalesced)
#pragma unroll
    for (int i = 0; i < 2; ++i) {
        const int idx = tid + 512 * i;
        slang[idx >> 8][idx & 255] = lang[idx];
    }
    __syncthreads();

    // Phase 1: warp w computes rows 8w..8w+7, two rows at a time (8 accums).
#pragma unroll
    for (int rp = 0; rp < 4; ++rp) {
        const int n0 = 8 * warp + 2 * rp;
        const float* w0 = Ws + (size_t)n0 * LANG_DIM;
        const float* w1 = w0 + LANG_DIM;

        float p[2][NB];
#pragma unroll
        for (int r = 0; r < 2; ++r)
#pragma unroll
            for (int b = 0; b < NB; ++b) p[r][b] = 0.0f;

#pragma unroll
        for (int j = 0; j < LANG_DIM / 32; ++j) {
            const int idx = lane + 32 * j;
            const float wv0 = w0[idx];
            const float wv1 = w1[idx];
#pragma unroll
            for (int b = 0; b < NB; ++b) {
                const float lv = slang[b][idx];
                p[0][b] += wv0 * lv;
                p[1][b] += wv1 * lv;
            }
        }
#pragma unroll
        for (int off = 16; off > 0; off >>= 1)
#pragma unroll
            for (int r = 0; r < 2; ++r)
#pragma unroll
                for (int b = 0; b < NB; ++b)
                    p[r][b] += __shfl_xor_sync(0xFFFFFFFFu, p[r][b], off);

        if (lane == 0) {
#pragma unroll
            for (int r = 0; r < 2; ++r) {
                const float bias = bs[n0 + r];
#pragma unroll
                for (int b = 0; b < NB; ++b)
                    actv[b][n0 + r] = p[r][b] + bias;
            }
        }
    }
    __syncthreads();

    // Phase 2: warp k<6 folds gamma/beta for all 4 batches.
    if (warp < NUM_OP) {
        const int k = warp;
        const float* wgr = Wg + k * NHIDDEN;
        const float* wbr = Wb + k * NHIDDEN;
        float pg[NB], pb[NB];
#pragma unroll
        for (int b = 0; b < NB; ++b) { pg[b] = 0.0f; pb[b] = 0.0f; }
#pragma unroll
        for (int j = 0; j < NHIDDEN / 32; ++j) {
            const int idx = lane + 32 * j;
            const float wgv = wgr[idx];
            const float wbv = wbr[idx];
#pragma unroll
            for (int b = 0; b < NB; ++b) {
                const float a = actv[b][idx];
                pg[b] += a * wgv;
                pb[b] += a * wbv;
            }
        }
#pragma unroll
        for (int off = 16; off > 0; off >>= 1)
#pragma unroll
            for (int b = 0; b < NB; ++b) {
                pg[b] += __shfl_xor_sync(0xFFFFFFFFu, pg[b], off);
                pb[b] += __shfl_xor_sync(0xFFFFFFFFu, pb[b], off);
            }
        if (lane == 0) {
            const float wr = Wr[k];
#pragma unroll
            for (int b = 0; b < NB; ++b) {
                g_gw[b][k] = (pg[b] + bg[k]) * wr;
                g_bw[b][k] = (pb[b] + bb[k]) * wr;
            }
        }
    } else if (warp == 6 && lane == 0) {
        float s = 0.0f;
#pragma unroll
        for (int k = 0; k < NUM_OP; ++k) s += Wr[k];
        g_wrsum = s;
        g_br = br[0];
    }
}

// ---------------------------------------------------------------------------
// Kernel 2: out[b,c,hw] = x[b,c,hw]*scale[b,hw] + shift[b,hw]
// Grid (16, 4, 16) = 1024 blocks x 256 threads, __launch_bounds__(256,8):
// regs capped at 32 -> 8 blocks/SM -> 1184 capacity -> ONE balanced wave.
// ---------------------------------------------------------------------------
#define CCHUNK 8
#define TPB 256

__global__ __launch_bounds__(TPB, 8) void main_kernel(const float* __restrict__ x,
                                                      const float* __restrict__ sem,
                                                      float* __restrict__ out) {
    const int b   = blockIdx.y;
    const int c0  = blockIdx.z * CCHUNK;
    const int hw4 = blockIdx.x * TPB + threadIdx.x;   // [0, HWSZ/4)

    float4 scale = make_float4(g_wrsum, g_wrsum, g_wrsum, g_wrsum);
    float4 shift = make_float4(g_br, g_br, g_br, g_br);

    const float4* semb =
        reinterpret_cast<const float4*>(sem + (size_t)b * SEM_CH * HWSZ + 2 * HWSZ) + hw4;
#pragma unroll
    for (int k = 0; k < NUM_OP; ++k) {
        const float gw = g_gw[b][k];
        const float bw = g_bw[b][k];
        const float4 s = __ldg(semb + (size_t)k * (HWSZ / 4));
        scale.x += gw * s.x;  scale.y += gw * s.y;
        scale.z += gw * s.z;  scale.w += gw * s.w;
        shift.x += bw * s.x;  shift.y += bw * s.y;
        shift.z += bw * s.z;  shift.w += bw * s.w;
    }

    const float4* xb = reinterpret_cast<const float4*>(x + (size_t)b * NC * HWSZ) + hw4;
    float4*       ob = reinterpret_cast<float4*>(out + (size_t)b * NC * HWSZ) + hw4;

#pragma unroll
    for (int c = c0; c < c0 + CCHUNK; ++c) {
        const float4 xv = __ldcs(xb + (size_t)c * (HWSZ / 4));
        float4 o;
        o.x = xv.x * scale.x + shift.x;
        o.y = xv.y * scale.y + shift.y;
        o.z = xv.z * scale.z + shift.z;
        o.w = xv.w * scale.w + shift.w;
        __stcs(ob + (size_t)c * (HWSZ / 4), o);
    }
}

// ---------------------------------------------------------------------------
extern "C" void kernel_launch(void* const* d_in, const int* in_sizes, int n_in,
                              void* d_out, int out_size) {
    const float* x    = (const float*)d_in[0];
    const float* lang = (const float*)d_in[1];
    const float* sem  = (const float*)d_in[2];
    const float* Ws   = (const float*)d_in[3];
    const float* bs   = (const float*)d_in[4];
    const float* Wg   = (const float*)d_in[5];
    const float* bg   = (const float*)d_in[6];
    const float* Wb   = (const float*)d_in[7];
    const float* bb   = (const float*)d_in[8];
    const float* Wr   = (const float*)d_in[9];
    const float* br   = (const float*)d_in[10];
    float* out = (float*)d_out;

    coef_kernel<<<1, 512>>>(lang, Ws, bs, Wg, bg, Wb, bb, Wr, br);

    dim3 grid(HWSZ / 4 / TPB, NB, NC / CCHUNK);
    main_kernel<<<grid, TPB>>>(x, sem, out);
}